// round 15
// baseline (speedup 1.0000x reference)
#include <cuda_runtime.h>

// Bloch-vector formulation (exact rewrite of the 4-qubit QCNN circuit):
//   n_enc = (sin(pi x1)cos(pi x2), sin(pi x1)sin(pi x2), cos(pi x1))
//   z_q = r_q . n_enc          (r_q = 3rd row of layer-1 gate Bloch rotation)
//   h_q = s_q . n_enc          (s_q = b_q*row1 - c_q*row2, observable folded)
//   Z0 = a0 z_a + h_a z_b      Z1 = a1 z_b + h_b z_a z_c
//   Z2 = a2 z_c + h_c z_b z_d  Z3 = a3 z_d + h_d z_c
// All CZ gates and the encoding RZ fold away exactly (diagonal phases /
// global phase). Verified at rel_err ~1.9e-6 across rounds 6-14.
//
// Converged configuration (session best: 6.50 us ncu / 6.62 us wall):
// 1 line/thread, 256-thread blocks, grid 1024, loads issued before the
// per-block constant precompute so DRAM latency overlaps it. Grid exactly
// covers the 262144 lines -> no bounds check.

__global__ __launch_bounds__(256)
void qcnn_kernel(const float* __restrict__ x, const float* __restrict__ w,
                 float* __restrict__ out) {
    // sc[q] = (r.x, r.y, r.z, a_q); sc[4+q] = (s.x, s.y, s.z, 0)
    __shared__ float4 sc[8];

    int tid = threadIdx.x;
    int t = blockIdx.x * 256 + tid;

    // w first: it heads the barrier-critical precompute chain.
    float wa1 = 0.f, wb1 = 0.f, wg1 = 0.f, wa2 = 0.f, wb2 = 0.f, wg2 = 0.f;
    if (tid < 4) {
        const float* wp = w + tid * 3;
        wa1 = __ldg(wp + 0);  wb1 = __ldg(wp + 1);  wg1 = __ldg(wp + 2);
        wa2 = __ldg(wp + 12); wb2 = __ldg(wp + 13); wg2 = __ldg(wp + 14);
    }

    // This thread's line: DRAM latency overlaps precompute + barrier.
    const float4* xb = (const float4*)(x + (size_t)t * 12);
    float4 F0 = __ldg(xb + 0), F1 = __ldg(xb + 1), F2 = __ldg(xb + 2);

    if (tid < 4) {
        int q = tid;
        // ---- layer-1 gate U1 = RZ(g)RY(b)RX(a): need u00, u10 only ----
        float sa, ca, sb, cb, sg, cg;
        __sincosf(0.5f * wa1, &sa, &ca);
        __sincosf(0.5f * wb1, &sb, &cb);
        __sincosf(0.5f * wg1, &sg, &cg);
        float m00r = cb * ca, m00i = sb * sa;
        float m10r = sb * ca, m10i = -cb * sa;
        float u00r = cg * m00r + sg * m00i, u00i = cg * m00i - sg * m00r;
        float u10r = cg * m10r - sg * m10i, u10i = cg * m10i + sg * m10r;
        // SU(2) -> quaternion (t,x,y,z): U = tI - i(x sx + y sy + z sz)
        float qt = u00r, qz = -u00i, qy = u10r, qx = -u10i;
        float r1x = 1.f - 2.f * (qy * qy + qz * qz);
        float r1y = 2.f * (qx * qy - qt * qz);
        float r1z = 2.f * (qx * qz + qt * qy);
        float r2x = 2.f * (qx * qy + qt * qz);
        float r2y = 1.f - 2.f * (qx * qx + qz * qz);
        float r2z = 2.f * (qy * qz - qt * qx);
        float r3x = 2.f * (qx * qz - qt * qy);
        float r3y = 2.f * (qy * qz + qt * qx);
        float r3z = 1.f - 2.f * (qx * qx + qy * qy);

        // ---- layer-2 gate U2 -> observable M = U2^dag Z U2 ----
        __sincosf(0.5f * wa2, &sa, &ca);
        __sincosf(0.5f * wb2, &sb, &cb);
        __sincosf(0.5f * wg2, &sg, &cg);
        float n00r = cb * ca, n00i = sb * sa;
        float n01r = -sb * ca, n01i = -cb * sa;
        float n10r = sb * ca, n10i = -cb * sa;
        float n11r = cb * ca, n11i = -sb * sa;
        float v00r = cg * n00r + sg * n00i, v00i = cg * n00i - sg * n00r;
        float v01r = cg * n01r + sg * n01i, v01i = cg * n01i - sg * n01r;
        float v10r = cg * n10r - sg * n10i, v10i = cg * n10i + sg * n10r;
        float v11r = cg * n11r - sg * n11i, v11i = cg * n11i + sg * n11r;
        float ma = v00r * v00r + v00i * v00i - v10r * v10r - v10i * v10i;
        float mb = v00r * v01r + v00i * v01i - (v10r * v11r + v10i * v11i);
        float nc = -(v00r * v01i - v00i * v01r - (v10r * v11i - v10i * v11r));

        sc[q]     = make_float4(r3x, r3y, r3z, ma);
        sc[4 + q] = make_float4(fmaf(mb, r1x, nc * r2x),
                                fmaf(mb, r1y, nc * r2y),
                                fmaf(mb, r1z, nc * r2z), 0.f);
    }
    __syncthreads();

    const float PI = 3.14159265358979323846f;

    float s1, c1, s2, c2;
    // ---- qubit 0 ----
    __sincosf(PI * F0.y, &s1, &c1);
    __sincosf(PI * F0.z, &s2, &c2);
    float xe = s1 * c2, ye = s1 * s2, ze = c1;
    float4 r = sc[0], s = sc[4];
    float za = fmaf(r.z, ze, fmaf(r.y, ye, r.x * xe));
    float ha = fmaf(s.z, ze, fmaf(s.y, ye, s.x * xe));
    float aza = r.w * za;
    // ---- qubit 1 ----
    __sincosf(PI * F1.x, &s1, &c1);
    __sincosf(PI * F1.y, &s2, &c2);
    xe = s1 * c2; ye = s1 * s2; ze = c1;
    r = sc[1]; s = sc[5];
    float zb = fmaf(r.z, ze, fmaf(r.y, ye, r.x * xe));
    float hb = fmaf(s.z, ze, fmaf(s.y, ye, s.x * xe));
    float azb = r.w * zb;
    // ---- qubit 2 ----
    __sincosf(PI * F1.w, &s1, &c1);
    __sincosf(PI * F2.x, &s2, &c2);
    xe = s1 * c2; ye = s1 * s2; ze = c1;
    r = sc[2]; s = sc[6];
    float zc = fmaf(r.z, ze, fmaf(r.y, ye, r.x * xe));
    float hc = fmaf(s.z, ze, fmaf(s.y, ye, s.x * xe));
    float azc = r.w * zc;
    // ---- qubit 3 ----
    __sincosf(PI * F2.z, &s1, &c1);
    __sincosf(PI * F2.w, &s2, &c2);
    xe = s1 * c2; ye = s1 * s2; ze = c1;
    r = sc[3]; s = sc[7];
    float zd = fmaf(r.z, ze, fmaf(r.y, ye, r.x * xe));
    float hd = fmaf(s.z, ze, fmaf(s.y, ye, s.x * xe));
    float azd = r.w * zd;

    float Z0 = fmaf(ha, zb, aza);
    float Z1 = fmaf(hb, za * zc, azb);
    float Z2 = fmaf(hc, zb * zd, azc);
    float Z3 = fmaf(hd, zc, azd);

    ((float4*)out)[t] = make_float4(Z0, Z1, Z2, Z3);
}

extern "C" void kernel_launch(void* const* d_in, const int* in_sizes, int n_in,
                              void* d_out, int out_size) {
    const float* x = (const float*)d_in[0];   // [128, 2048, 4, 3] f32
    const float* w = (const float*)d_in[1];   // [2, 4, 3] f32
    float* out = (float*)d_out;               // [128, 2048, 4] f32

    int nlines = in_sizes[0] / 12;            // 262144 (exact multiple of 256)
    int block = 256;
    int grid = nlines / block;                // 1024
    qcnn_kernel<<<grid, block>>>(x, w, out);
}

// round 16
// speedup vs baseline: 1.0631x; 1.0631x over previous
#include <cuda_runtime.h>

// Bloch-vector formulation (exact rewrite of the 4-qubit QCNN circuit):
//   n_enc = (sin(pi x1)cos(pi x2), sin(pi x1)sin(pi x2), cos(pi x1))
//   z_q = r_q . n_enc          (r_q = 3rd row of layer-1 gate Bloch rotation)
//   h_q = s_q . n_enc          (s_q = b_q*row1 - c_q*row2, observable folded)
//   Z0 = a0 z_a + h_a z_b      Z1 = a1 z_b + h_b z_a z_c
//   Z2 = a2 z_c + h_c z_b z_d  Z3 = a3 z_d + h_d z_c
// All CZ gates and the encoding RZ fold away exactly (diagonal phases /
// global phase). Verified at rel_err ~1.9e-6 across rounds 6-15.
//
// FINAL converged configuration (session best: 6.496 us ncu / 6.656 us wall):
// 1 line/thread, 256-thread blocks, grid 1024, loads issued before the
// per-block constant precompute so DRAM latency overlaps it. Kernel is at a
// latency-composition floor: DRAM ~24%, MUFU ~28%, FMA ~7%, no pipe saturated.

__global__ __launch_bounds__(256)
void qcnn_kernel(const float* __restrict__ x, const float* __restrict__ w,
                 float* __restrict__ out, int n) {
    // sc[q] = (r.x, r.y, r.z, a_q); sc[4+q] = (s.x, s.y, s.z, 0)
    __shared__ float4 sc[8];

    int tid = threadIdx.x;
    int t = blockIdx.x * 256 + tid;

    // Issue global loads first: DRAM latency overlaps precompute + barrier.
    const float4* xb = (const float4*)(x + (size_t)t * 12);
    float4 F0 = __ldg(xb + 0), F1 = __ldg(xb + 1), F2 = __ldg(xb + 2);

    if (tid < 4) {
        int q = tid;
        // ---- layer-1 gate U1 = RZ(g)RY(b)RX(a): need u00, u10 only ----
        float a1 = w[q * 3 + 0], b1 = w[q * 3 + 1], g1 = w[q * 3 + 2];
        float sa, ca, sb, cb, sg, cg;
        __sincosf(0.5f * a1, &sa, &ca);
        __sincosf(0.5f * b1, &sb, &cb);
        __sincosf(0.5f * g1, &sg, &cg);
        float m00r = cb * ca, m00i = sb * sa;
        float m10r = sb * ca, m10i = -cb * sa;
        float u00r = cg * m00r + sg * m00i, u00i = cg * m00i - sg * m00r;
        float u10r = cg * m10r - sg * m10i, u10i = cg * m10i + sg * m10r;
        // SU(2) -> quaternion (t,x,y,z): U = tI - i(x sx + y sy + z sz)
        float qt = u00r, qz = -u00i, qy = u10r, qx = -u10i;
        float r1x = 1.f - 2.f * (qy * qy + qz * qz);
        float r1y = 2.f * (qx * qy - qt * qz);
        float r1z = 2.f * (qx * qz + qt * qy);
        float r2x = 2.f * (qx * qy + qt * qz);
        float r2y = 1.f - 2.f * (qx * qx + qz * qz);
        float r2z = 2.f * (qy * qz - qt * qx);
        float r3x = 2.f * (qx * qz - qt * qy);
        float r3y = 2.f * (qy * qz + qt * qx);
        float r3z = 1.f - 2.f * (qx * qx + qy * qy);

        // ---- layer-2 gate U2 -> observable M = U2^dag Z U2 ----
        float a2 = w[12 + q * 3 + 0], b2 = w[12 + q * 3 + 1], g2 = w[12 + q * 3 + 2];
        __sincosf(0.5f * a2, &sa, &ca);
        __sincosf(0.5f * b2, &sb, &cb);
        __sincosf(0.5f * g2, &sg, &cg);
        float n00r = cb * ca, n00i = sb * sa;
        float n01r = -sb * ca, n01i = -cb * sa;
        float n10r = sb * ca, n10i = -cb * sa;
        float n11r = cb * ca, n11i = -sb * sa;
        float v00r = cg * n00r + sg * n00i, v00i = cg * n00i - sg * n00r;
        float v01r = cg * n01r + sg * n01i, v01i = cg * n01i - sg * n01r;
        float v10r = cg * n10r - sg * n10i, v10i = cg * n10i + sg * n10r;
        float v11r = cg * n11r - sg * n11i, v11i = cg * n11i + sg * n11r;
        float ma = v00r * v00r + v00i * v00i - v10r * v10r - v10i * v10i;
        float mb = v00r * v01r + v00i * v01i - (v10r * v11r + v10i * v11i);
        float mc = v00r * v01i - v00i * v01r - (v10r * v11i - v10i * v11r);

        sc[q]     = make_float4(r3x, r3y, r3z, ma);
        sc[4 + q] = make_float4(mb * r1x - mc * r2x,
                                mb * r1y - mc * r2y,
                                mb * r1z - mc * r2z, 0.f);
    }
    __syncthreads();

    if (t >= n) return;

    const float PI = 3.14159265358979323846f;

    float s1, c1, s2, c2;
    // ---- qubit 0 ----
    __sincosf(PI * F0.y, &s1, &c1);
    __sincosf(PI * F0.z, &s2, &c2);
    float xe = s1 * c2, ye = s1 * s2, ze = c1;
    float4 r = sc[0], s = sc[4];
    float za = fmaf(r.z, ze, fmaf(r.y, ye, r.x * xe));
    float ha = fmaf(s.z, ze, fmaf(s.y, ye, s.x * xe));
    float aza = r.w * za;
    // ---- qubit 1 ----
    __sincosf(PI * F1.x, &s1, &c1);
    __sincosf(PI * F1.y, &s2, &c2);
    xe = s1 * c2; ye = s1 * s2; ze = c1;
    r = sc[1]; s = sc[5];
    float zb = fmaf(r.z, ze, fmaf(r.y, ye, r.x * xe));
    float hb = fmaf(s.z, ze, fmaf(s.y, ye, s.x * xe));
    float azb = r.w * zb;
    // ---- qubit 2 ----
    __sincosf(PI * F1.w, &s1, &c1);
    __sincosf(PI * F2.x, &s2, &c2);
    xe = s1 * c2; ye = s1 * s2; ze = c1;
    r = sc[2]; s = sc[6];
    float zc = fmaf(r.z, ze, fmaf(r.y, ye, r.x * xe));
    float hc = fmaf(s.z, ze, fmaf(s.y, ye, s.x * xe));
    float azc = r.w * zc;
    // ---- qubit 3 ----
    __sincosf(PI * F2.z, &s1, &c1);
    __sincosf(PI * F2.w, &s2, &c2);
    xe = s1 * c2; ye = s1 * s2; ze = c1;
    r = sc[3]; s = sc[7];
    float zd = fmaf(r.z, ze, fmaf(r.y, ye, r.x * xe));
    float hd = fmaf(s.z, ze, fmaf(s.y, ye, s.x * xe));
    float azd = r.w * zd;

    float Z0 = fmaf(ha, zb, aza);
    float Z1 = fmaf(hb, za * zc, azb);
    float Z2 = fmaf(hc, zb * zd, azc);
    float Z3 = fmaf(hd, zc, azd);

    ((float4*)out)[t] = make_float4(Z0, Z1, Z2, Z3);
}

extern "C" void kernel_launch(void* const* d_in, const int* in_sizes, int n_in,
                              void* d_out, int out_size) {
    const float* x = (const float*)d_in[0];   // [128, 2048, 4, 3] f32
    const float* w = (const float*)d_in[1];   // [2, 4, 3] f32
    float* out = (float*)d_out;               // [128, 2048, 4] f32

    int nlines = in_sizes[0] / 12;            // 262144
    int block = 256;
    int grid = (nlines + block - 1) / block;  // 1024
    qcnn_kernel<<<grid, block>>>(x, w, out, nlines);
}